// round 1
// baseline (speedup 1.0000x reference)
#include <cuda_runtime.h>
#include <math.h>

// Problem constants (fixed shapes)
constexpr int NX = 128, NY = 128, NZ = 128;
constexpr int NA = 96, NU = 128, NV = 128, NSTEPS = 128;
constexpr int PITCH = 129;                 // smem row pitch (floats) to stagger banks
constexpr int ACHUNKS = 3;                 // 96 angles / 32 per block
constexpr int A_PER_BLOCK = NA / ACHUNKS;  // 32

// T = 0.5*sqrt((127*1)^2 + (127*1)^2), delta_t = 2T/128  (computed in double, cast f32
// to match the reference's python-float -> float32 promotion)
constexpr float TF  = (float)89.80256121069154;   // T
constexpr float DTF = (float)1.4031650189170553;  // delta_t
constexpr float T0F = -TF + 0.5f * DTF;           // t_0 = -T + 0.5*dt

// 8 MB scratch: vol transposed to [z][y][x] (x contiguous)
__device__ float g_vol_t[NZ * NY * NX];

// ---------------------------------------------------------------------------
// Transpose vol[(x*NY + y)*NZ + z]  ->  g_vol_t[(z*NY + y)*NX + x]
// One 32x32 (x,z) tile per block, y = blockIdx.z.
// ---------------------------------------------------------------------------
__global__ void transpose_kernel(const float* __restrict__ vol) {
    __shared__ float tile[32][33];
    const int y  = blockIdx.z;
    const int x0 = blockIdx.x * 32;
    const int z0 = blockIdx.y * 32;
    const int tx = threadIdx.x;      // 0..31
    const int ty = threadIdx.y;      // 0..7

#pragma unroll
    for (int j = 0; j < 32; j += 8) {
        int x = x0 + ty + j;
        int z = z0 + tx;
        tile[ty + j][tx] = vol[(x * NY + y) * NZ + z];   // coalesced in z
    }
    __syncthreads();
#pragma unroll
    for (int j = 0; j < 32; j += 8) {
        int z = z0 + ty + j;
        int x = x0 + tx;
        g_vol_t[(z * NY + y) * NX + x] = tile[tx][ty + j];   // coalesced in x
    }
}

// ---------------------------------------------------------------------------
// Conservative step-range for  val(i) = A + i*d  to lie in (-1, 128).
// Widened by 1 on each side; out-of-range steps compute exact zeros anyway.
// ---------------------------------------------------------------------------
__device__ __forceinline__ void slab_range(float A, float d, int& lo, int& hi) {
    if (fabsf(d) < 1e-8f) {
        if (A > -1.0f && A < 128.0f) { lo = 0; hi = NSTEPS - 1; }
        else                         { lo = 1; hi = 0; }
        return;
    }
    float inv = 1.0f / d;
    float i1 = (-1.0f - A) * inv;
    float i2 = (128.0f - A) * inv;
    float flo = fminf(i1, i2);
    float fhi = fmaxf(i1, i2);
    lo = max(0, __float2int_rd(flo) - 1);          // saturating F2I
    hi = min(NSTEPS - 1, __float2int_ru(fhi) + 1);
}

// ---------------------------------------------------------------------------
// Projector: one block = (angle chunk, z slice). Slice cached in smem.
// Thread -> u = tid&127, handles angles achunk*32 + (tid>>7) + 2*j.
// ---------------------------------------------------------------------------
__global__ __launch_bounds__(256) void joseph_proj_kernel(
    const float* __restrict__ angles, float* __restrict__ out) {
    extern __shared__ float sm[];   // [NY][PITCH]

    const int z      = blockIdx.y;
    const int achunk = blockIdx.x;

    // Load slice z into shared memory (coalesced; pitch-129 layout)
    const float* slice = g_vol_t + z * (NY * NX);
    for (int i = threadIdx.x; i < NY * NX; i += 256) {
        int y = i >> 7;
        int x = i & 127;
        sm[y * PITCH + x] = slice[i];
    }
    __syncthreads();

    const int   u    = threadIdx.x & 127;
    const int   asub = threadIdx.x >> 7;    // 0..1
    const float uu   = (float)u - 63.5f;

#pragma unroll 1
    for (int j = 0; j < A_PER_BLOCK / 2; ++j) {
        const int a = achunk * A_PER_BLOCK + asub + 2 * j;
        float s, c;
        sincosf(angles[a], &s, &c);

        // x(t) = 63.5 - uu*s + t*c ;  y(t) = 63.5 + uu*c + t*s
        const float xA = fmaf(T0F, c, 63.5f - uu * s);  // value at step i=0
        const float yA = fmaf(T0F, s, 63.5f + uu * c);
        const float dx = DTF * c;
        const float dy = DTF * s;

        int lox, hix, loy, hiy;
        slab_range(xA, dx, lox, hix);
        slab_range(yA, dy, loy, hiy);
        const int ilo = max(lox, loy);
        const int ihi = min(hix, hiy);

        float acc = 0.0f;
#pragma unroll 4
        for (int i = ilo; i <= ihi; ++i) {
            const float fi = (float)i;
            const float x = fmaf(fi, dx, xA);
            const float y = fmaf(fi, dy, yA);

            const int ix = __float2int_rd(x);
            const int iy = __float2int_rd(y);
            const float fx = x - (float)ix;
            const float fy = y - (float)iy;

            // zero-padded corner weights (matches F.grid_sample padding='zeros')
            const float wx0 = ((unsigned)ix        < 128u) ? (1.0f - fx) : 0.0f;
            const float wx1 = ((unsigned)(ix + 1)  < 128u) ? fx          : 0.0f;
            const float wy0 = ((unsigned)iy        < 128u) ? (1.0f - fy) : 0.0f;
            const float wy1 = ((unsigned)(iy + 1)  < 128u) ? fy          : 0.0f;

            const int cx0 = min(max(ix,     0), 127);
            const int cx1 = min(max(ix + 1, 0), 127);
            const int cy0 = min(max(iy,     0), 127);
            const int cy1 = min(max(iy + 1, 0), 127);

            const float* r0 = sm + cy0 * PITCH;
            const float* r1 = sm + cy1 * PITCH;
            const float v00 = r0[cx0];
            const float v01 = r0[cx1];
            const float v10 = r1[cx0];
            const float v11 = r1[cx1];

            const float m0 = fmaf(wy1, v10, wy0 * v00);
            const float m1 = fmaf(wy1, v11, wy0 * v01);
            acc = fmaf(wx0, m0, acc);
            acc = fmaf(wx1, m1, acc);
        }

        // out shape (U, A, V): out[u][a][z]
        out[(u * NA + a) * NV + z] = acc * DTF;
    }
}

// ---------------------------------------------------------------------------
extern "C" void kernel_launch(void* const* d_in, const int* in_sizes, int n_in,
                              void* d_out, int out_size) {
    (void)in_sizes; (void)n_in; (void)out_size;
    const float* vol    = (const float*)d_in[0];
    const float* angles = (const float*)d_in[1];
    float*       out    = (float*)d_out;

    constexpr int SMEM_BYTES = NY * PITCH * (int)sizeof(float);  // 66048
    static bool attr_set = false;
    if (!attr_set) {
        cudaFuncSetAttribute(joseph_proj_kernel,
                             cudaFuncAttributeMaxDynamicSharedMemorySize, SMEM_BYTES);
        attr_set = true;
    }

    dim3 tgrid(NX / 32, NZ / 32, NY);
    dim3 tblock(32, 8);
    transpose_kernel<<<tgrid, tblock>>>(vol);

    dim3 pgrid(ACHUNKS, NZ);
    joseph_proj_kernel<<<pgrid, 256, SMEM_BYTES>>>(angles, out);
}

// round 3
// speedup vs baseline: 1.3457x; 1.3457x over previous
#include <cuda_runtime.h>
#include <math.h>

// Problem constants (fixed shapes)
constexpr int NX = 128, NY = 128, NZ = 128;
constexpr int NA = 96, NU = 128, NV = 128, NSTEPS = 128;
constexpr int ACHUNKS = 3;                 // 96 angles / 32 per block
constexpr int A_PER_BLOCK = NA / ACHUNKS;  // 32

// Zero-padded shared tile: data at [OFS .. OFS+127], zero border.
// slab_range widening admits coords in [OFS-1-2dt, OFS+128+2dt] = [0.19, 134.81]
// with dt=1.4032, so all indices (incl. +1 corners) lie in [0, 135].
constexpr int OFS      = 4;
constexpr int SM_ROWS  = 136;
constexpr int PITCH    = 137;              // odd pitch (137 mod 32 = 9)
constexpr int SM_ELEMS = SM_ROWS * PITCH;  // 18632 floats = 74528 B

// T = 0.5*sqrt(127^2 + 127^2), delta_t = 2T/128 (double -> f32, matching the
// reference's python-float -> float32 promotion)
constexpr float TF  = (float)89.80256121069154;   // T
constexpr float DTF = (float)1.4031650189170553;  // delta_t
constexpr float T0F = -TF + 0.5f * DTF;           // t_0 = -T + 0.5*dt

// 8 MB scratch: vol transposed to [z][y][x] (x contiguous)
__device__ float g_vol_t[NZ * NY * NX];

// ---------------------------------------------------------------------------
// Transpose vol[(x*NY + y)*NZ + z]  ->  g_vol_t[(z*NY + y)*NX + x]
// ---------------------------------------------------------------------------
__global__ void transpose_kernel(const float* __restrict__ vol) {
    __shared__ float tile[32][33];
    const int y  = blockIdx.z;
    const int x0 = blockIdx.x * 32;
    const int z0 = blockIdx.y * 32;
    const int tx = threadIdx.x;      // 0..31
    const int ty = threadIdx.y;      // 0..7

#pragma unroll
    for (int j = 0; j < 32; j += 8) {
        int x = x0 + ty + j;
        int z = z0 + tx;
        tile[ty + j][tx] = vol[(x * NY + y) * NZ + z];   // coalesced in z
    }
    __syncthreads();
#pragma unroll
    for (int j = 0; j < 32; j += 8) {
        int z = z0 + ty + j;
        int x = x0 + tx;
        g_vol_t[(z * NY + y) * NX + x] = tile[tx][ty + j];   // coalesced in x
    }
}

// ---------------------------------------------------------------------------
// Conservative step range for val(i) = A + i*d to lie in (lo_b, hi_b).
// Widened by 1 step each side; out-of-range steps read zero border anyway.
// ---------------------------------------------------------------------------
__device__ __forceinline__ void slab_range(float A, float d, float lo_b, float hi_b,
                                           int& lo, int& hi) {
    if (fabsf(d) < 1e-8f) {
        if (A > lo_b && A < hi_b) { lo = 0; hi = NSTEPS - 1; }
        else                      { lo = 1; hi = 0; }
        return;
    }
    float inv = 1.0f / d;
    float i1 = (lo_b - A) * inv;
    float i2 = (hi_b - A) * inv;
    // clamp to avoid int wrap after saturated conversion
    float flo = fmaxf(fminf(i1, i2), -1e9f);
    float fhi = fminf(fmaxf(i1, i2),  1e9f);
    lo = max(0, __float2int_rd(flo) - 1);
    hi = min(NSTEPS - 1, __float2int_ru(fhi) + 1);
}

// ---------------------------------------------------------------------------
// Projector: one block = (angle chunk, z slice). Zero-padded slice in smem.
// ---------------------------------------------------------------------------
__global__ __launch_bounds__(256) void joseph_proj_kernel(
    const float* __restrict__ angles, float* __restrict__ out) {
    extern __shared__ float sm[];   // [SM_ROWS][PITCH], zero border

    const int z      = blockIdx.y;
    const int achunk = blockIdx.x;

    // zero-fill (borders), then place data at +OFS
    for (int i = threadIdx.x; i < SM_ELEMS; i += 256) sm[i] = 0.0f;
    __syncthreads();
    const float* slice = g_vol_t + z * (NY * NX);
    for (int i = threadIdx.x; i < NY * NX; i += 256) {
        int y = i >> 7;
        int x = i & 127;
        sm[(y + OFS) * PITCH + (x + OFS)] = slice[i];
    }
    __syncthreads();

    const int   u    = threadIdx.x & 127;
    const int   asub = threadIdx.x >> 7;    // 0..1
    const float uu   = (float)u - 63.5f;
    const float CTR  = 63.5f + (float)OFS;  // shifted center

#pragma unroll 1
    for (int j = 0; j < A_PER_BLOCK / 2; ++j) {
        const int a = achunk * A_PER_BLOCK + asub + 2 * j;
        float s, c;
        sincosf(angles[a], &s, &c);

        // shifted coords: x(i) = CTR - uu*s + (T0 + i*dt)*c, similarly y
        const float xA = fmaf(T0F, c, CTR - uu * s);
        const float yA = fmaf(T0F, s, CTR + uu * c);
        const float dx = DTF * c;
        const float dy = DTF * s;

        int lox, hix, loy, hiy;
        slab_range(xA, dx, (float)OFS - 1.0f, (float)OFS + 128.0f, lox, hix);
        slab_range(yA, dy, (float)OFS - 1.0f, (float)OFS + 128.0f, loy, hiy);
        const int ilo = max(lox, loy);
        const int ihi = min(hix, hiy);

        float acc = 0.0f;
        float fi  = (float)ilo;
#pragma unroll 4
        for (int i = ilo; i <= ihi; ++i, fi += 1.0f) {
            const float x = fmaf(fi, dx, xA);   // strictly positive
            const float y = fmaf(fi, dy, yA);

            const int ix = (int)x;              // trunc == floor (positive)
            const int iy = (int)y;
            const float fx = x - (float)ix;
            const float fy = y - (float)iy;

            const float* r = sm + (iy * PITCH + ix);
            const float v00 = r[0];
            const float v01 = r[1];
            const float v10 = r[PITCH];
            const float v11 = r[PITCH + 1];

            // unmasked bilinear (zero border supplies padding semantics)
            const float m0 = fmaf(fy, v10 - v00, v00);
            const float m1 = fmaf(fy, v11 - v01, v01);
            acc = fmaf(fx, m1 - m0, acc + m0);
        }

        // out shape (U, A, V): out[u][a][z]
        out[(u * NA + a) * NV + z] = acc * DTF;
    }
}

// ---------------------------------------------------------------------------
extern "C" void kernel_launch(void* const* d_in, const int* in_sizes, int n_in,
                              void* d_out, int out_size) {
    (void)in_sizes; (void)n_in; (void)out_size;
    const float* vol    = (const float*)d_in[0];
    const float* angles = (const float*)d_in[1];
    float*       out    = (float*)d_out;

    constexpr int SMEM_BYTES = SM_ELEMS * (int)sizeof(float);  // 74528
    static bool attr_set = false;
    if (!attr_set) {
        cudaFuncSetAttribute(joseph_proj_kernel,
                             cudaFuncAttributeMaxDynamicSharedMemorySize, SMEM_BYTES);
        attr_set = true;
    }

    dim3 tgrid(NX / 32, NZ / 32, NY);
    dim3 tblock(32, 8);
    transpose_kernel<<<tgrid, tblock>>>(vol);

    dim3 pgrid(ACHUNKS, NZ);
    joseph_proj_kernel<<<pgrid, 256, SMEM_BYTES>>>(angles, out);
}

// round 4
// speedup vs baseline: 1.5442x; 1.1475x over previous
#include <cuda_runtime.h>
#include <math.h>

// Problem constants (fixed shapes)
constexpr int NX = 128, NY = 128, NZ = 128;
constexpr int NA = 96, NU = 128, NV = 128, NSTEPS = 128;
constexpr int NZP = NZ / 2;                // 64 z-pairs
constexpr int ACHUNKS = 2;                 // 96 angles / 48 per block
constexpr int A_PER_BLOCK = NA / ACHUNKS;  // 48

// Zero-padded shared tile (float2 = two z-slices interleaved).
// slab_range widening admits coords in [OFS-1-2dt, OFS+128+2dt] = [0.19, 134.81]
// with dt=1.4032, so all indices (incl. +1 corners) lie in [0, 135].
constexpr int OFS      = 4;
constexpr int SM_ROWS  = 136;
constexpr int PITCH    = 137;              // odd pitch
constexpr int SM_ELEMS = SM_ROWS * PITCH;  // 18632 float2 = 149056 B

// T = 0.5*sqrt(127^2 + 127^2), delta_t = 2T/128 (double -> f32)
constexpr float TF  = (float)89.80256121069154;
constexpr float DTF = (float)1.4031650189170553;
constexpr float T0F = -TF + 0.5f * DTF;

// 8 MB scratch: vol as [z-pair][y][x] float2 (z-parity interleaved, x contiguous)
__device__ float2 g_vol2[NZP * NY * NX];

// ---------------------------------------------------------------------------
// Transpose vol[(x*NY + y)*NZ + z] -> g_vol2[(zp*NY + y)*NX + x] = {z even, z odd}
// ---------------------------------------------------------------------------
__global__ void transpose_kernel(const float* __restrict__ vol) {
    __shared__ float tile[32][33];           // [x local][z local]
    const int y  = blockIdx.z;
    const int x0 = blockIdx.x * 32;
    const int z0 = blockIdx.y * 32;
    const int tx = threadIdx.x;              // 0..31
    const int ty = threadIdx.y;              // 0..7

#pragma unroll
    for (int j = 0; j < 32; j += 8) {
        int x = x0 + ty + j;
        int z = z0 + tx;
        tile[ty + j][tx] = vol[(x * NY + y) * NZ + z];   // coalesced in z
    }
    __syncthreads();
#pragma unroll
    for (int j = 0; j < 16; j += 8) {
        int zpl = ty + j;                    // 0..15 (z-pair within tile)
        int x   = x0 + tx;
        int zp  = (z0 >> 1) + zpl;
        g_vol2[(zp * NY + y) * NX + x] =
            make_float2(tile[tx][2 * zpl], tile[tx][2 * zpl + 1]);  // coalesced f2
    }
}

// ---------------------------------------------------------------------------
// Conservative step range for val(i) = A + i*d to lie in (lo_b, hi_b).
// ---------------------------------------------------------------------------
__device__ __forceinline__ void slab_range(float A, float d, float lo_b, float hi_b,
                                           int& lo, int& hi) {
    if (fabsf(d) < 1e-8f) {
        if (A > lo_b && A < hi_b) { lo = 0; hi = NSTEPS - 1; }
        else                      { lo = 1; hi = 0; }
        return;
    }
    float inv = 1.0f / d;
    float i1 = (lo_b - A) * inv;
    float i2 = (hi_b - A) * inv;
    float flo = fmaxf(fminf(i1, i2), -1e9f);
    float fhi = fminf(fmaxf(i1, i2),  1e9f);
    lo = max(0, __float2int_rd(flo) - 1);
    hi = min(NSTEPS - 1, __float2int_ru(fhi) + 1);
}

// ---------------------------------------------------------------------------
// Projector: one block = (angle chunk, z-pair). Two zero-padded slices (float2)
// in smem; each inner step produces two outputs (z even/odd).
// ---------------------------------------------------------------------------
__global__ __launch_bounds__(256) void joseph_proj_kernel(
    const float* __restrict__ angles, float* __restrict__ out) {
    extern __shared__ float2 sm2[];   // [SM_ROWS][PITCH], zero border

    const int zp     = blockIdx.y;
    const int achunk = blockIdx.x;

    // zero-fill (borders), then place data at +OFS
    for (int i = threadIdx.x; i < SM_ELEMS; i += 256) sm2[i] = make_float2(0.f, 0.f);
    __syncthreads();
    const float2* slice = g_vol2 + zp * (NY * NX);
    for (int i = threadIdx.x; i < NY * NX; i += 256) {
        int y = i >> 7;
        int x = i & 127;
        sm2[(y + OFS) * PITCH + (x + OFS)] = slice[i];
    }
    __syncthreads();

    const int   u    = threadIdx.x & 127;
    const int   asub = threadIdx.x >> 7;    // 0..1
    const float uu   = (float)u - 63.5f;
    const float CTR  = 63.5f + (float)OFS;

#pragma unroll 1
    for (int j = 0; j < A_PER_BLOCK / 2; ++j) {
        const int a = achunk * A_PER_BLOCK + asub + 2 * j;
        float s, c;
        sincosf(angles[a], &s, &c);

        const float xA = fmaf(T0F, c, CTR - uu * s);
        const float yA = fmaf(T0F, s, CTR + uu * c);
        const float dx = DTF * c;
        const float dy = DTF * s;

        int lox, hix, loy, hiy;
        slab_range(xA, dx, (float)OFS - 1.0f, (float)OFS + 128.0f, lox, hix);
        slab_range(yA, dy, (float)OFS - 1.0f, (float)OFS + 128.0f, loy, hiy);
        const int ilo = max(lox, loy);
        const int ihi = min(hix, hiy);

        float acc0 = 0.0f, acc1 = 0.0f;
        float fi = (float)ilo;
#pragma unroll 4
        for (int i = ilo; i <= ihi; ++i, fi += 1.0f) {
            const float x = fmaf(fi, dx, xA);   // strictly positive
            const float y = fmaf(fi, dy, yA);

            const int ix = (int)x;              // trunc == floor (positive)
            const int iy = (int)y;
            const float fx = x - (float)ix;
            const float fy = y - (float)iy;

            const float2* r = sm2 + (iy * PITCH + ix);
            const float2 v00 = r[0];
            const float2 v01 = r[1];
            const float2 v10 = r[PITCH];
            const float2 v11 = r[PITCH + 1];

            // unmasked bilinear for both z slices
            const float m0x = fmaf(fy, v10.x - v00.x, v00.x);
            const float m1x = fmaf(fy, v11.x - v01.x, v01.x);
            const float m0y = fmaf(fy, v10.y - v00.y, v00.y);
            const float m1y = fmaf(fy, v11.y - v01.y, v01.y);
            acc0 = fmaf(fx, m1x - m0x, acc0 + m0x);
            acc1 = fmaf(fx, m1y - m0y, acc1 + m0y);
        }

        // out shape (U, A, V): out[u][a][2zp], [u][a][2zp+1] -> one float2 store
        float2 res = make_float2(acc0 * DTF, acc1 * DTF);
        *reinterpret_cast<float2*>(out + (u * NA + a) * NV + 2 * zp) = res;
    }
}

// ---------------------------------------------------------------------------
extern "C" void kernel_launch(void* const* d_in, const int* in_sizes, int n_in,
                              void* d_out, int out_size) {
    (void)in_sizes; (void)n_in; (void)out_size;
    const float* vol    = (const float*)d_in[0];
    const float* angles = (const float*)d_in[1];
    float*       out    = (float*)d_out;

    constexpr int SMEM_BYTES = SM_ELEMS * (int)sizeof(float2);  // 149056
    static bool attr_set = false;
    if (!attr_set) {
        cudaFuncSetAttribute(joseph_proj_kernel,
                             cudaFuncAttributeMaxDynamicSharedMemorySize, SMEM_BYTES);
        attr_set = true;
    }

    dim3 tgrid(NX / 32, NZ / 32, NY);
    dim3 tblock(32, 8);
    transpose_kernel<<<tgrid, tblock>>>(vol);

    dim3 pgrid(ACHUNKS, NZP);
    joseph_proj_kernel<<<pgrid, 256, SMEM_BYTES>>>(angles, out);
}

// round 5
// speedup vs baseline: 1.6499x; 1.0685x over previous
#include <cuda_runtime.h>
#include <math.h>

// Problem constants (fixed shapes)
constexpr int NX = 128, NY = 128, NZ = 128;
constexpr int NA = 96, NU = 128, NV = 128, NSTEPS = 128;
constexpr int NZP = NZ / 2;                // 64 z-pairs
constexpr int ACHUNKS = 2;                 // 96 angles / 48 per block
constexpr int A_PER_BLOCK = NA / ACHUNKS;  // 48
constexpr int THREADS = 512;
constexpr int ASUB = THREADS / 128;        // 4 angle sub-lanes
constexpr int J_ITERS = A_PER_BLOCK / ASUB; // 12 angles per thread

// Zero-padded shared tile (float2 = two z-slices interleaved).
// slab_range widening admits coords in [OFS-1-2dt, OFS+128+2dt] = [0.19, 134.81]
// so all indices (incl. +1 corners) lie in [0, 135].
constexpr int OFS      = 4;
constexpr int SM_ROWS  = 136;
constexpr int PITCH    = 137;              // odd pitch
constexpr int SM_ELEMS = SM_ROWS * PITCH;  // 18632 float2 = 149056 B

// T = 0.5*sqrt(127^2 + 127^2), delta_t = 2T/128 (double -> f32)
constexpr float TF  = (float)89.80256121069154;
constexpr float DTF = (float)1.4031650189170553;
constexpr float T0F = -TF + 0.5f * DTF;

// 8 MB scratch: vol as [z-pair][y][x] float2 (z-parity interleaved, x contiguous)
__device__ float2 g_vol2[NZP * NY * NX];

// ---------------------------------------------------------------------------
// Transpose vol[(x*NY + y)*NZ + z] -> g_vol2[(zp*NY + y)*NX + x] = {z even, z odd}
// ---------------------------------------------------------------------------
__global__ void transpose_kernel(const float* __restrict__ vol) {
    __shared__ float tile[32][33];           // [x local][z local]
    const int y  = blockIdx.z;
    const int x0 = blockIdx.x * 32;
    const int z0 = blockIdx.y * 32;
    const int tx = threadIdx.x;              // 0..31
    const int ty = threadIdx.y;              // 0..7

#pragma unroll
    for (int j = 0; j < 32; j += 8) {
        int x = x0 + ty + j;
        int z = z0 + tx;
        tile[ty + j][tx] = vol[(x * NY + y) * NZ + z];   // coalesced in z
    }
    __syncthreads();
#pragma unroll
    for (int j = 0; j < 16; j += 8) {
        int zpl = ty + j;                    // 0..15 (z-pair within tile)
        int x   = x0 + tx;
        int zp  = (z0 >> 1) + zpl;
        g_vol2[(zp * NY + y) * NX + x] =
            make_float2(tile[tx][2 * zpl], tile[tx][2 * zpl + 1]);  // coalesced f2
    }
}

// ---------------------------------------------------------------------------
// Conservative step range for val(i) = A + i*d to lie in (lo_b, hi_b).
// ---------------------------------------------------------------------------
__device__ __forceinline__ void slab_range(float A, float d, float lo_b, float hi_b,
                                           int& lo, int& hi) {
    if (fabsf(d) < 1e-8f) {
        if (A > lo_b && A < hi_b) { lo = 0; hi = NSTEPS - 1; }
        else                      { lo = 1; hi = 0; }
        return;
    }
    float inv = 1.0f / d;
    float i1 = (lo_b - A) * inv;
    float i2 = (hi_b - A) * inv;
    float flo = fmaxf(fminf(i1, i2), -1e9f);
    float fhi = fminf(fmaxf(i1, i2),  1e9f);
    lo = max(0, __float2int_rd(flo) - 1);
    hi = min(NSTEPS - 1, __float2int_ru(fhi) + 1);
}

// ---------------------------------------------------------------------------
// Projector: one block = (angle chunk, z-pair). Two zero-padded slices (float2)
// in smem; each inner step produces two outputs (z even/odd).
// 512 threads: u = tid&127, asub = tid>>7 (4 angle sub-lanes).
// ---------------------------------------------------------------------------
__global__ __launch_bounds__(THREADS) void joseph_proj_kernel(
    const float* __restrict__ angles, float* __restrict__ out) {
    extern __shared__ float2 sm2[];   // [SM_ROWS][PITCH], zero border

    const int zp     = blockIdx.y;
    const int achunk = blockIdx.x;

    // zero-fill (borders), then place data at +OFS
    for (int i = threadIdx.x; i < SM_ELEMS; i += THREADS) sm2[i] = make_float2(0.f, 0.f);
    __syncthreads();
    const float2* slice = g_vol2 + zp * (NY * NX);
    for (int i = threadIdx.x; i < NY * NX; i += THREADS) {
        int y = i >> 7;
        int x = i & 127;
        sm2[(y + OFS) * PITCH + (x + OFS)] = slice[i];
    }
    __syncthreads();

    const int   u    = threadIdx.x & 127;
    const int   asub = threadIdx.x >> 7;    // 0..3
    const float uu   = (float)u - 63.5f;
    const float CTR  = 63.5f + (float)OFS;

#pragma unroll 1
    for (int j = 0; j < J_ITERS; ++j) {
        const int a = achunk * A_PER_BLOCK + asub + ASUB * j;
        float s, c;
        sincosf(angles[a], &s, &c);

        const float xA = fmaf(T0F, c, CTR - uu * s);
        const float yA = fmaf(T0F, s, CTR + uu * c);
        const float dx = DTF * c;
        const float dy = DTF * s;

        int lox, hix, loy, hiy;
        slab_range(xA, dx, (float)OFS - 1.0f, (float)OFS + 128.0f, lox, hix);
        slab_range(yA, dy, (float)OFS - 1.0f, (float)OFS + 128.0f, loy, hiy);
        const int ilo = max(lox, loy);
        const int ihi = min(hix, hiy);

        float acc0 = 0.0f, acc1 = 0.0f;
        float fi = (float)ilo;
#pragma unroll 4
        for (int i = ilo; i <= ihi; ++i, fi += 1.0f) {
            const float x = fmaf(fi, dx, xA);   // strictly positive
            const float y = fmaf(fi, dy, yA);

            const int ix = (int)x;              // trunc == floor (positive)
            const int iy = (int)y;
            const float fx = x - (float)ix;
            const float fy = y - (float)iy;

            const float2* r = sm2 + (iy * PITCH + ix);
            const float2 v00 = r[0];
            const float2 v01 = r[1];
            const float2 v10 = r[PITCH];
            const float2 v11 = r[PITCH + 1];

            // unmasked bilinear for both z slices
            const float m0x = fmaf(fy, v10.x - v00.x, v00.x);
            const float m1x = fmaf(fy, v11.x - v01.x, v01.x);
            const float m0y = fmaf(fy, v10.y - v00.y, v00.y);
            const float m1y = fmaf(fy, v11.y - v01.y, v01.y);
            acc0 = fmaf(fx, m1x - m0x, acc0 + m0x);
            acc1 = fmaf(fx, m1y - m0y, acc1 + m0y);
        }

        // out shape (U, A, V): out[u][a][2zp], [u][a][2zp+1] -> one float2 store
        float2 res = make_float2(acc0 * DTF, acc1 * DTF);
        *reinterpret_cast<float2*>(out + (u * NA + a) * NV + 2 * zp) = res;
    }
}

// ---------------------------------------------------------------------------
extern "C" void kernel_launch(void* const* d_in, const int* in_sizes, int n_in,
                              void* d_out, int out_size) {
    (void)in_sizes; (void)n_in; (void)out_size;
    const float* vol    = (const float*)d_in[0];
    const float* angles = (const float*)d_in[1];
    float*       out    = (float*)d_out;

    constexpr int SMEM_BYTES = SM_ELEMS * (int)sizeof(float2);  // 149056
    static bool attr_set = false;
    if (!attr_set) {
        cudaFuncSetAttribute(joseph_proj_kernel,
                             cudaFuncAttributeMaxDynamicSharedMemorySize, SMEM_BYTES);
        attr_set = true;
    }

    dim3 tgrid(NX / 32, NZ / 32, NY);
    dim3 tblock(32, 8);
    transpose_kernel<<<tgrid, tblock>>>(vol);

    dim3 pgrid(ACHUNKS, NZP);
    joseph_proj_kernel<<<pgrid, THREADS, SMEM_BYTES>>>(angles, out);
}